// round 8
// baseline (speedup 1.0000x reference)
#include <cuda_runtime.h>

#define BINS 10
#define TPB  256
#define BPSM 4
#define GRID (152 * BPSM)   // one wave on GB300 (152 SMs)

// Global scratch (allocation-free __device__ globals, zero-init at load;
// last block re-zeros them each run so graph replays stay deterministic).
__device__ double       g_cnt[BINS];
__device__ double       g_sum[BINS];
__device__ unsigned int g_done;

__device__ __forceinline__ float rcp_fast(float x) { float r; asm("rcp.approx.f32 %0, %1;" : "=f"(r) : "f"(x)); return r; }
__device__ __forceinline__ float lg2_fast(float x) { float r; asm("lg2.approx.f32 %0, %1;" : "=f"(r) : "f"(x)); return r; }
__device__ __forceinline__ float ex2_fast(float x) { float r; asm("ex2.approx.f32 %0, %1;" : "=f"(r) : "f"(x)); return r; }

__device__ __forceinline__ unsigned smem_off(const void* p)
{
    unsigned a;
    asm("{ .reg .u64 t; cvta.to.shared.u64 t, %1; cvt.u32.u64 %0, t; }"
        : "=r"(a) : "l"(p));
    return a;
}

// One element (same numerics as R7, new accumulation):
//   s = x ^ mask;  e = exp(-|x|);  d = 1+e;  u = 9.9999*rcp(d)
//   us = (s>=0) ? u : 9.9999-u;  bin = trunc(us) in [0,9]
//   bce = (s>=0 ? |x| : 0) + ln2*lg2(d)
// Accumulate with NO-RETURN shared atomics into two 4-byte-stride arrays:
//   cnt[bin][tid] (u32) at coff = cbase + bin*1024   (bank = tid: conflict-free)
//   sum[bin][tid] (f32) at coff + 10240
// red.shared is fire-and-forget: no LDS->FADD->STS dependency chain at all.
#define GHM_ELEM(xval, msk, cbase)                                       \
    asm volatile(                                                        \
        "{\n\t"                                                          \
        ".reg .f32 ax,w,e,d,r,u,v,us,m,lg,b;\n\t"                        \
        ".reg .pred p;\n\t"                                              \
        ".reg .b32 sx,bin,offc,offs;\n\t"                                \
        "xor.b32 sx, %0, %1;\n\t"                                        \
        "abs.f32 ax, %2;\n\t"                                            \
        "mul.f32 w, ax, 0fBFB8AA3B;\n\t"                                 \
        "ex2.approx.f32 e, w;\n\t"                                       \
        "add.f32 d, e, 0f3F800000;\n\t"                                  \
        "rcp.approx.f32 r, d;\n\t"                                       \
        "mul.f32 u, r, 0f411FFF97;\n\t"                                  \
        "sub.f32 v, 0f411FFF97, u;\n\t"                                  \
        "setp.ge.s32 p, sx, 0;\n\t"                                      \
        "selp.f32 us, u, v, p;\n\t"                                      \
        "cvt.rzi.s32.f32 bin, us;\n\t"                                   \
        "selp.f32 m, ax, 0f00000000, p;\n\t"                             \
        "lg2.approx.f32 lg, d;\n\t"                                      \
        "fma.rn.f32 b, lg, 0f3F317218, m;\n\t"                           \
        "mad.lo.s32 offc, bin, 1024, %3;\n\t"                            \
        "red.shared.add.u32 [offc], %4;\n\t"                             \
        "add.s32 offs, offc, 10240;\n\t"                                 \
        "red.shared.add.f32 [offs], b;\n\t"                              \
        "}\n\t"                                                          \
        :: "r"(__float_as_int(xval)), "r"(msk), "f"(xval), "r"(cbase),   \
           "r"(1)                                                        \
        : "memory")

__global__ void __launch_bounds__(TPB, BPSM)
ghm_fused(const float4* __restrict__ x4,
          const int4*   __restrict__ t4,
          int nquads, int nrows,
          const float* __restrict__ xs,
          const int*   __restrict__ ts,
          float* __restrict__ out)
{
    // cnt[BINS][TPB] u32 then sum[BINS][TPB] f32, contiguous (10240 B apart).
    __shared__ unsigned s_cnt[BINS][TPB];
    __shared__ float    s_sum[BINS][TPB];
    __shared__ int      s_last;
    const int tid = threadIdx.x;
#pragma unroll
    for (int b = 0; b < BINS; b++) {
        s_cnt[b][tid] = 0u;
        s_sum[b][tid] = 0.0f;
    }
    __syncthreads();

    const unsigned cbase = smem_off(&s_cnt[0][tid]);   // sum array = cbase + 10240

    // 2-deep software pipeline: prefetch iteration i+1's 48 bytes into
    // registers while the element bodies for iteration i execute.
    const int stride = GRID * TPB;
    int i = blockIdx.x * TPB + tid;
    bool valid = (i < nquads);
    float4 xa, xb; int4 tv;
    if (valid) {
        xa = __ldcs(&x4[2 * i]);
        xb = __ldcs(&x4[2 * i + 1]);
        tv = __ldcs(&t4[i]);
    }
    while (valid) {
        int inext = i + stride;
        bool vnext = (inext < nquads);
        float4 nxa, nxb; int4 ntv;
        if (vnext) {
            nxa = __ldcs(&x4[2 * inext]);
            nxb = __ldcs(&x4[2 * inext + 1]);
            ntv = __ldcs(&t4[inext]);
        }

        // Row sign masks: class1 mask = t<<31, class0 mask = that ^ signbit.
        unsigned ma1 = ((unsigned)tv.x) << 31, ma0 = ma1 ^ 0x80000000u;
        unsigned mb1 = ((unsigned)tv.y) << 31, mb0 = mb1 ^ 0x80000000u;
        unsigned mc1 = ((unsigned)tv.z) << 31, mc0 = mc1 ^ 0x80000000u;
        unsigned md1 = ((unsigned)tv.w) << 31, md0 = md1 ^ 0x80000000u;

        GHM_ELEM(xa.x, ma0, cbase);
        GHM_ELEM(xa.y, ma1, cbase);
        GHM_ELEM(xa.z, mb0, cbase);
        GHM_ELEM(xa.w, mb1, cbase);
        GHM_ELEM(xb.x, mc0, cbase);
        GHM_ELEM(xb.y, mc1, cbase);
        GHM_ELEM(xb.z, md0, cbase);
        GHM_ELEM(xb.w, md1, cbase);

        xa = nxa; xb = nxb; tv = ntv;
        i = inext; valid = vnext;
    }

    // Tail rows (nrows % 4 != 0): direct double atomics, block 0 only.
    if (blockIdx.x == 0) {
        int tail0 = nquads * 4;
        for (int rowi = tail0 + tid; rowi < nrows; rowi += TPB) {
            int t = ts[rowi];
            for (int c = 0; c < 2; c++) {
                float x = xs[rowi * 2 + c];
                unsigned mask = ((t == c) ? 0x80000000u : 0u);
                int   sx = __float_as_int(x) ^ (int)mask;
                float ax = fabsf(x);
                float e  = ex2_fast(ax * -1.4426950408889634f);
                float d  = 1.0f + e;
                float u  = rcp_fast(d) * 9.9999f;
                bool pos = (sx >= 0);
                float us = pos ? u : (9.9999f - u);
                int  bin = (int)us;
                float m  = pos ? ax : 0.0f;
                float bce = fmaf(lg2_fast(d), 0.69314718055994531f, m);
                atomicAdd(&g_cnt[bin], 1.0);
                atomicAdd(&g_sum[bin], (double)bce);
            }
        }
    }
    __syncthreads();   // BAR drains pending shared-memory atomics

    // Tree-reduce 256 columns x 10 bins (counts in u32, sums in f32).
    for (int off = TPB / 2; off > 0; off >>= 1) {
        if (tid < off) {
#pragma unroll
            for (int b = 0; b < BINS; b++) {
                s_cnt[b][tid] += s_cnt[b][tid + off];
                s_sum[b][tid] += s_sum[b][tid + off];
            }
        }
        __syncthreads();
    }

    if (tid < BINS) {
        atomicAdd(&g_cnt[tid], (double)s_cnt[tid][0]);
        atomicAdd(&g_sum[tid], (double)s_sum[tid][0]);
    }
    __syncthreads();

    // Last-block finalize (and reset for the next graph replay).
    if (tid == 0) {
        __threadfence();
        unsigned old = atomicAdd(&g_done, 1u);
        s_last = (old == GRID - 1) ? 1 : 0;
    }
    __syncthreads();

    if (s_last && tid == 0) {
        __threadfence();
        volatile double* vc = g_cnt;
        volatile double* vs = g_sum;
        double cnt[BINS], sum[BINS];
        double nonempty = 0.0;
        for (int b = 0; b < BINS; b++) {
            cnt[b] = vc[b];
            sum[b] = vs[b];
            if (cnt[b] > 0.0) nonempty += 1.0;
        }
        // mean(weight*bce) = (1/N) * sum_b (N/gd_b) * S_b = sum_b S_b / gd_b
        double loss = 0.0;
        for (int b = 0; b < BINS; b++) {
            double gd = cnt[b] * nonempty;
            if (gd < 1e-4) gd = 1e-4;
            loss += sum[b] / gd;
        }
        out[0] = (float)loss;
        for (int b = 0; b < BINS; b++) { vc[b] = 0.0; vs[b] = 0.0; }
        __threadfence();
        g_done = 0u;
    }
}

extern "C" void kernel_launch(void* const* d_in, const int* in_sizes, int n_in,
                              void* d_out, int out_size)
{
    // x: [B,2] float32 (2B elems), target: [B] int32 (B elems) — identify by count.
    const float* x;
    const int*   t;
    int nrows;
    if (in_sizes[0] >= 2 * in_sizes[1]) {
        x = (const float*)d_in[0];
        t = (const int*)d_in[1];
        nrows = in_sizes[1];
    } else {
        x = (const float*)d_in[1];
        t = (const int*)d_in[0];
        nrows = in_sizes[0];
    }
    int nquads = nrows >> 2;

    ghm_fused<<<GRID, TPB>>>((const float4*)x, (const int4*)t, nquads, nrows,
                             x, t, (float*)d_out);
}

// round 9
// speedup vs baseline: 1.0605x; 1.0605x over previous
#include <cuda_runtime.h>

#define BINS 10
#define TPB  128
#define BPSM 5
#define GRID (152 * BPSM)   // one wave of 128-thread blocks on GB300

// Global scratch (allocation-free __device__ globals, zero-init at load;
// last block re-zeros them each run so graph replays stay deterministic).
__device__ double       g_cnt[BINS];
__device__ double       g_sum[BINS];
__device__ unsigned int g_done;

// Pure (non-volatile) single-op asm: compiler remains free to schedule.
__device__ __forceinline__ float rcp_fast(float x) { float r; asm("rcp.approx.f32 %0, %1;" : "=f"(r) : "f"(x)); return r; }
__device__ __forceinline__ float lg2_fast(float x) { float r; asm("lg2.approx.f32 %0, %1;" : "=f"(r) : "f"(x)); return r; }
__device__ __forceinline__ float ex2_fast(float x) { float r; asm("ex2.approx.f32 %0, %1;" : "=f"(r) : "f"(x)); return r; }

// Same numerics as R7 (identical rel_err):
//   s = x ^ mask;  |s| = |x|;  e = exp(-|x|);  d = 1+e;  u = 9.9999*rcp(d)
//   us = (s>=0) ? u : 9.9999-u;  bin = trunc(us) in [0,9]
//   bce = (s>=0 ? |x| : 0) + ln2 * lg2(d)
// hist is a float2[BINS][TPB] column pointer (&h[0][tid]): bank = tid.
__device__ __forceinline__ void ghm_elem(float x, unsigned mask, float2* hcol)
{
    int   sx = __float_as_int(x) ^ (int)mask;
    float ax = fabsf(x);
    float e  = ex2_fast(ax * -1.4426950408889634f);
    float d  = 1.0f + e;
    float u  = rcp_fast(d) * 9.9999f;
    bool pos = (sx >= 0);
    float us = pos ? u : (9.9999f - u);
    int  bin = (int)us;
    float m  = pos ? ax : 0.0f;
    float bce = fmaf(lg2_fast(d), 0.69314718055994531f, m);
    float2 h = hcol[bin * TPB];
    h.x += 1.0f;
    h.y += bce;
    hcol[bin * TPB] = h;
}

__global__ void __launch_bounds__(TPB, BPSM)
ghm_fused(const float4* __restrict__ x4,
          const int4*   __restrict__ t4,
          int nquads, int nrows,
          const float* __restrict__ xs,
          const int*   __restrict__ ts,
          float* __restrict__ out)
{
    // FOUR distinct shared arrays: provably non-aliasing objects, so the
    // compiler can overlap the four RMW chains (2 elements each per iter)
    // instead of serializing one 8-deep LDS->FADD->STS chain.
    __shared__ float2 hist0[BINS][TPB];
    __shared__ float2 hist1[BINS][TPB];
    __shared__ float2 hist2[BINS][TPB];
    __shared__ float2 hist3[BINS][TPB];
    __shared__ int    s_last;
    const int tid = threadIdx.x;
#pragma unroll
    for (int b = 0; b < BINS; b++) {
        hist0[b][tid] = make_float2(0.0f, 0.0f);
        hist1[b][tid] = make_float2(0.0f, 0.0f);
        hist2[b][tid] = make_float2(0.0f, 0.0f);
        hist3[b][tid] = make_float2(0.0f, 0.0f);
    }
    __syncthreads();

    float2* hc0 = &hist0[0][tid];
    float2* hc1 = &hist1[0][tid];
    float2* hc2 = &hist2[0][tid];
    float2* hc3 = &hist3[0][tid];

    // 2-deep software pipeline: prefetch iteration i+1's 48 bytes into
    // registers while the element bodies for iteration i execute.
    const int stride = GRID * TPB;
    int i = blockIdx.x * TPB + tid;
    bool valid = (i < nquads);
    float4 xa, xb; int4 tv;
    if (valid) {
        xa = __ldcs(&x4[2 * i]);
        xb = __ldcs(&x4[2 * i + 1]);
        tv = __ldcs(&t4[i]);
    }
    while (valid) {
        int inext = i + stride;
        bool vnext = (inext < nquads);
        float4 nxa, nxb; int4 ntv;
        if (vnext) {
            nxa = __ldcs(&x4[2 * inext]);
            nxb = __ldcs(&x4[2 * inext + 1]);
            ntv = __ldcs(&t4[inext]);
        }

        // Row sign masks: class1 mask = t<<31, class0 mask = that ^ signbit.
        unsigned ma1 = ((unsigned)tv.x) << 31, ma0 = ma1 ^ 0x80000000u;
        unsigned mb1 = ((unsigned)tv.y) << 31, mb0 = mb1 ^ 0x80000000u;
        unsigned mc1 = ((unsigned)tv.z) << 31, mc0 = mc1 ^ 0x80000000u;
        unsigned md1 = ((unsigned)tv.w) << 31, md0 = md1 ^ 0x80000000u;

        ghm_elem(xa.x, ma0, hc0);
        ghm_elem(xa.y, ma1, hc1);
        ghm_elem(xa.z, mb0, hc2);
        ghm_elem(xa.w, mb1, hc3);
        ghm_elem(xb.x, mc0, hc0);
        ghm_elem(xb.y, mc1, hc1);
        ghm_elem(xb.z, md0, hc2);
        ghm_elem(xb.w, md1, hc3);

        xa = nxa; xb = nxb; tv = ntv;
        i = inext; valid = vnext;
    }

    // Tail rows (nrows % 4 != 0): direct double atomics, block 0 only.
    if (blockIdx.x == 0) {
        int tail0 = nquads * 4;
        for (int rowi = tail0 + tid; rowi < nrows; rowi += TPB) {
            int t = ts[rowi];
            for (int c = 0; c < 2; c++) {
                float x = xs[rowi * 2 + c];
                unsigned mask = ((t == c) ? 0x80000000u : 0u);
                int   sx = __float_as_int(x) ^ (int)mask;
                float ax = fabsf(x);
                float e  = ex2_fast(ax * -1.4426950408889634f);
                float d  = 1.0f + e;
                float u  = rcp_fast(d) * 9.9999f;
                bool pos = (sx >= 0);
                float us = pos ? u : (9.9999f - u);
                int  bin = (int)us;
                float m  = pos ? ax : 0.0f;
                float bce = fmaf(lg2_fast(d), 0.69314718055994531f, m);
                atomicAdd(&g_cnt[bin], 1.0);
                atomicAdd(&g_sum[bin], (double)bce);
            }
        }
    }
    __syncthreads();

    // Fold copies 1..3 into copy 0, then tree-reduce 128 columns x 10 bins.
#pragma unroll
    for (int b = 0; b < BINS; b++) {
        float2 a = hist0[b][tid];
        float2 c1 = hist1[b][tid];
        float2 c2 = hist2[b][tid];
        float2 c3 = hist3[b][tid];
        hist0[b][tid] = make_float2(a.x + c1.x + c2.x + c3.x,
                                    a.y + c1.y + c2.y + c3.y);
    }
    __syncthreads();
    for (int off = TPB / 2; off > 0; off >>= 1) {
        if (tid < off) {
#pragma unroll
            for (int b = 0; b < BINS; b++) {
                float2 a = hist0[b][tid];
                float2 c = hist0[b][tid + off];
                hist0[b][tid] = make_float2(a.x + c.x, a.y + c.y);
            }
        }
        __syncthreads();
    }

    if (tid < BINS) {
        atomicAdd(&g_cnt[tid], (double)hist0[tid][0].x);
        atomicAdd(&g_sum[tid], (double)hist0[tid][0].y);
    }
    __syncthreads();

    // Last-block finalize (and reset for the next graph replay).
    if (tid == 0) {
        __threadfence();
        unsigned old = atomicAdd(&g_done, 1u);
        s_last = (old == GRID - 1) ? 1 : 0;
    }
    __syncthreads();

    if (s_last && tid == 0) {
        __threadfence();
        volatile double* vc = g_cnt;
        volatile double* vs = g_sum;
        double cnt[BINS], sum[BINS];
        double nonempty = 0.0;
        for (int b = 0; b < BINS; b++) {
            cnt[b] = vc[b];
            sum[b] = vs[b];
            if (cnt[b] > 0.0) nonempty += 1.0;
        }
        // mean(weight*bce) = (1/N) * sum_b (N/gd_b) * S_b = sum_b S_b / gd_b
        double loss = 0.0;
        for (int b = 0; b < BINS; b++) {
            double gd = cnt[b] * nonempty;
            if (gd < 1e-4) gd = 1e-4;
            loss += sum[b] / gd;
        }
        out[0] = (float)loss;
        for (int b = 0; b < BINS; b++) { vc[b] = 0.0; vs[b] = 0.0; }
        __threadfence();
        g_done = 0u;
    }
}

extern "C" void kernel_launch(void* const* d_in, const int* in_sizes, int n_in,
                              void* d_out, int out_size)
{
    // x: [B,2] float32 (2B elems), target: [B] int32 (B elems) — identify by count.
    const float* x;
    const int*   t;
    int nrows;
    if (in_sizes[0] >= 2 * in_sizes[1]) {
        x = (const float*)d_in[0];
        t = (const int*)d_in[1];
        nrows = in_sizes[1];
    } else {
        x = (const float*)d_in[1];
        t = (const int*)d_in[0];
        nrows = in_sizes[0];
    }
    int nquads = nrows >> 2;

    ghm_fused<<<GRID, TPB>>>((const float4*)x, (const int4*)t, nquads, nrows,
                             x, t, (float*)d_out);
}

// round 10
// speedup vs baseline: 1.1323x; 1.0677x over previous
#include <cuda_runtime.h>

#define BINS 10
#define TPB  256
#define BPSM 8
#define GRID (152 * BPSM)   // 8 blocks/SM -> 64 warps/SM (100% occupancy)

// Global scratch (allocation-free __device__ globals, zero-init at load;
// last block re-zeros them each run so graph replays stay deterministic).
__device__ double       g_cnt[BINS];
__device__ double       g_sum[BINS];
__device__ unsigned int g_done;

__device__ __forceinline__ float rcp_fast(float x) { float r; asm("rcp.approx.f32 %0, %1;" : "=f"(r) : "f"(x)); return r; }
__device__ __forceinline__ float lg2_fast(float x) { float r; asm("lg2.approx.f32 %0, %1;" : "=f"(r) : "f"(x)); return r; }
__device__ __forceinline__ float ex2_fast(float x) { float r; asm("ex2.approx.f32 %0, %1;" : "=f"(r) : "f"(x)); return r; }

// s = x ^ mask (mask = target-match << 31);  |s| = |x|
//   e = exp(-|x|);  d = 1+e;  u = 9.9999*rcp(d)
//   us = (s>=0) ? u : 9.9999-u;  bin = trunc(us) in [0,9]
//   bce = (s>=0 ? |x| : 0) + ln2*lg2(d)
__device__ __forceinline__ void ghm_elem(float x, unsigned mask, float2 (*hist)[TPB], int tid)
{
    int   sx = __float_as_int(x) ^ (int)mask;
    float ax = fabsf(x);
    float e  = ex2_fast(ax * -1.4426950408889634f);
    float d  = 1.0f + e;
    float u  = rcp_fast(d) * 9.9999f;
    bool pos = (sx >= 0);
    float us = pos ? u : (9.9999f - u);
    int  bin = (int)us;
    float m  = pos ? ax : 0.0f;
    float bce = fmaf(lg2_fast(d), 0.69314718055994531f, m);
    float2 h = hist[bin][tid];
    h.x += 1.0f;
    h.y += bce;
    hist[bin][tid] = h;
}

__global__ void __launch_bounds__(TPB, BPSM)
ghm_fused(const float4* __restrict__ x4,
          const int2*   __restrict__ t2,
          int npairs, int nrows,
          const float* __restrict__ xs,
          const int*   __restrict__ ts,
          float* __restrict__ out)
{
    // Single privatized histogram: hist[bin][tid], float2 = (count, bce_sum).
    // Address stride 8B, bank = tid (mod 32): conflict-free for any bin mix.
    __shared__ float2 hist[BINS][TPB];
    __shared__ int    s_last;
    const int tid = threadIdx.x;
#pragma unroll
    for (int b = 0; b < BINS; b++) hist[b][tid] = make_float2(0.0f, 0.0f);
    __syncthreads();

    // Simple grid-stride loop, 2 rows (4 elements) per iteration.
    // x4[i] is lane-contiguous (fully coalesced 512B/warp), t2[i] 256B/warp.
    // Latency hiding comes from 64 warps/SM, not from manual pipelining.
    const int stride = GRID * TPB;
    for (int i = blockIdx.x * TPB + tid; i < npairs; i += stride) {
        float4 xv = x4[i];   // rows 2i (xv.x, xv.y) and 2i+1 (xv.z, xv.w)
        int2   tv = t2[i];

        unsigned m1a = ((unsigned)tv.x) << 31, m0a = m1a ^ 0x80000000u;
        unsigned m1b = ((unsigned)tv.y) << 31, m0b = m1b ^ 0x80000000u;

        ghm_elem(xv.x, m0a, hist, tid);
        ghm_elem(xv.y, m1a, hist, tid);
        ghm_elem(xv.z, m0b, hist, tid);
        ghm_elem(xv.w, m1b, hist, tid);
    }

    // Tail row (nrows odd): block 0 only, direct double atomics.
    if (blockIdx.x == 0 && tid == 0 && (nrows & 1)) {
        int rowi = nrows - 1;
        int t = ts[rowi];
        for (int c = 0; c < 2; c++) {
            float x = xs[rowi * 2 + c];
            unsigned mask = ((t == c) ? 0x80000000u : 0u);
            int   sx = __float_as_int(x) ^ (int)mask;
            float ax = fabsf(x);
            float e  = ex2_fast(ax * -1.4426950408889634f);
            float d  = 1.0f + e;
            float u  = rcp_fast(d) * 9.9999f;
            bool pos = (sx >= 0);
            float us = pos ? u : (9.9999f - u);
            int  bin = (int)us;
            float m  = pos ? ax : 0.0f;
            float bce = fmaf(lg2_fast(d), 0.69314718055994531f, m);
            atomicAdd(&g_cnt[bin], 1.0);
            atomicAdd(&g_sum[bin], (double)bce);
        }
    }
    __syncthreads();

    // Tree-reduce 256 columns x 10 bins.
    for (int off = TPB / 2; off > 0; off >>= 1) {
        if (tid < off) {
#pragma unroll
            for (int b = 0; b < BINS; b++) {
                float2 a = hist[b][tid];
                float2 c = hist[b][tid + off];
                hist[b][tid] = make_float2(a.x + c.x, a.y + c.y);
            }
        }
        __syncthreads();
    }

    if (tid < BINS) {
        atomicAdd(&g_cnt[tid], (double)hist[tid][0].x);
        atomicAdd(&g_sum[tid], (double)hist[tid][0].y);
    }
    __syncthreads();

    // Last-block finalize (and reset for the next graph replay).
    if (tid == 0) {
        __threadfence();
        unsigned old = atomicAdd(&g_done, 1u);
        s_last = (old == GRID - 1) ? 1 : 0;
    }
    __syncthreads();

    if (s_last && tid == 0) {
        __threadfence();
        volatile double* vc = g_cnt;
        volatile double* vs = g_sum;
        double cnt[BINS], sum[BINS];
        double nonempty = 0.0;
        for (int b = 0; b < BINS; b++) {
            cnt[b] = vc[b];
            sum[b] = vs[b];
            if (cnt[b] > 0.0) nonempty += 1.0;
        }
        // mean(weight*bce) = (1/N) * sum_b (N/gd_b) * S_b = sum_b S_b / gd_b
        double loss = 0.0;
        for (int b = 0; b < BINS; b++) {
            double gd = cnt[b] * nonempty;
            if (gd < 1e-4) gd = 1e-4;
            loss += sum[b] / gd;
        }
        out[0] = (float)loss;
        for (int b = 0; b < BINS; b++) { vc[b] = 0.0; vs[b] = 0.0; }
        __threadfence();
        g_done = 0u;
    }
}

extern "C" void kernel_launch(void* const* d_in, const int* in_sizes, int n_in,
                              void* d_out, int out_size)
{
    // x: [B,2] float32 (2B elems), target: [B] int32 (B elems) — identify by count.
    const float* x;
    const int*   t;
    int nrows;
    if (in_sizes[0] >= 2 * in_sizes[1]) {
        x = (const float*)d_in[0];
        t = (const int*)d_in[1];
        nrows = in_sizes[1];
    } else {
        x = (const float*)d_in[1];
        t = (const int*)d_in[0];
        nrows = in_sizes[0];
    }
    int npairs = nrows >> 1;   // 2 rows (4 elements) per iteration

    ghm_fused<<<GRID, TPB>>>((const float4*)x, (const int2*)t, npairs, nrows,
                             x, t, (float*)d_out);
}